// round 14
// baseline (speedup 1.0000x reference)
#include <cuda_runtime.h>

#define Ln 16384
#define BATCH 64
#define NT 1024
#define HALF 8192
#define CHUNK 8              // HALF / NT
#define NBLK 128
#define NIMF 6
#define MAXIT 12
#define TOLF 0.05
#define NEG_INF (-3.402823466e38f)
#define POS_INF (3.402823466e38f)
#define FNONE_L (-1048576.f)
#define FNONE_R (1048576.f)
#define CACHE_NONE (-2147483647)
#define IDX(i) ((i)+((i)>>4))
#define PADL (HALF+(HALF>>4))   // 8704

__device__ unsigned g_ep[NBLK];      // main (global) epoch
__device__ unsigned g_ep2[NBLK];     // pairwise exchange epoch
__device__ unsigned g_epf[NBLK];     // fallback exchange epoch
__device__ float g_part[2][4][NBLK];
__device__ float g_ex[2][NBLK][10];
__device__ float g_fb[2][NBLK][2];
__device__ float g_edgeF[2][NBLK];
__device__ float g_edgeL[2][NBLK];
__device__ float g_res[BATCH*Ln];

__global__ void emd_init() {
  if (threadIdx.x < NBLK) { g_ep[threadIdx.x] = 0u; g_ep2[threadIdx.x] = 0u; g_epf[threadIdx.x] = 0u; }
}

// ---------- block primitives (NT = 1024) ----------

__device__ __forceinline__ float bscan_ex(float v, int ismax, float* s_w) {
  const float ident = ismax ? NEG_INF : POS_INF;
  int lane = threadIdx.x & 31, wid = threadIdx.x >> 5;
  __syncthreads();
  float incl = v;
#pragma unroll
  for (int o = 1; o < 32; o <<= 1) {
    float u = __shfl_up_sync(0xffffffffu, incl, o);
    if (lane >= o) incl = ismax ? fmaxf(incl, u) : fminf(incl, u);
  }
  if (lane == 31) s_w[wid] = incl;
  __syncthreads();
  if (wid == 0) {
    float wi = s_w[lane];
#pragma unroll
    for (int o = 1; o < 32; o <<= 1) {
      float u = __shfl_up_sync(0xffffffffu, wi, o);
      if (lane >= o) wi = ismax ? fmaxf(wi, u) : fminf(wi, u);
    }
    float we = __shfl_up_sync(0xffffffffu, wi, 1);
    if (lane == 0) we = ident;
    s_w[lane] = we;
  }
  __syncthreads();
  float e = __shfl_up_sync(0xffffffffu, incl, 1);
  if (lane == 0) e = ident;
  float wp = s_w[wid];
  return ismax ? fmaxf(wp, e) : fminf(wp, e);
}

// fused quad scan: exclusive prefix-MAX on (v1,v2), exclusive suffix-MIN on (v3,v4),
// plus block-wide inclusive totals. 2 internal syncs. Needs barrier-protected s_w.
__device__ __forceinline__ void bscan4(float v1, float v2, float v3, float v4, float* s_w,
                                       float& e1, float& e2, float& e3, float& e4,
                                       float& tot1, float& tot2, float& tot3, float& tot4) {
  int lane = threadIdx.x & 31, wid = threadIdx.x >> 5;
  float a1 = v1, a2 = v2, b1 = v3, b2 = v4;
#pragma unroll
  for (int o = 1; o < 32; o <<= 1) {
    float u1 = __shfl_up_sync(0xffffffffu, a1, o);
    float u2 = __shfl_up_sync(0xffffffffu, a2, o);
    float d1 = __shfl_down_sync(0xffffffffu, b1, o);
    float d2 = __shfl_down_sync(0xffffffffu, b2, o);
    if (lane >= o) { a1 = fmaxf(a1, u1); a2 = fmaxf(a2, u2); }
    if (lane < 32 - o) { b1 = fminf(b1, d1); b2 = fminf(b2, d2); }
  }
  if (lane == 31) { s_w[wid] = a1; s_w[32 + wid] = a2; }
  if (lane == 0)  { s_w[64 + wid] = b1; s_w[96 + wid] = b2; }
  __syncthreads();
  if (wid == 0) {
    float w1 = s_w[lane], w2 = s_w[32 + lane], w3 = s_w[64 + lane], w4 = s_w[96 + lane];
#pragma unroll
    for (int o = 1; o < 32; o <<= 1) {
      float u1 = __shfl_up_sync(0xffffffffu, w1, o);
      float u2 = __shfl_up_sync(0xffffffffu, w2, o);
      float d3 = __shfl_down_sync(0xffffffffu, w3, o);
      float d4 = __shfl_down_sync(0xffffffffu, w4, o);
      if (lane >= o) { w1 = fmaxf(w1, u1); w2 = fmaxf(w2, u2); }
      if (lane < 32 - o) { w3 = fminf(w3, d3); w4 = fminf(w4, d4); }
    }
    if (lane == 31) { s_w[128] = w1; s_w[129] = w2; }
    if (lane == 0)  { s_w[130] = w3; s_w[131] = w4; }
    float x1 = __shfl_up_sync(0xffffffffu, w1, 1);
    float x2 = __shfl_up_sync(0xffffffffu, w2, 1);
    float x3 = __shfl_down_sync(0xffffffffu, w3, 1);
    float x4 = __shfl_down_sync(0xffffffffu, w4, 1);
    if (lane == 0)  { x1 = NEG_INF; x2 = NEG_INF; }
    if (lane == 31) { x3 = POS_INF; x4 = POS_INF; }
    s_w[lane] = x1; s_w[32 + lane] = x2; s_w[64 + lane] = x3; s_w[96 + lane] = x4;
  }
  __syncthreads();
  float p1 = __shfl_up_sync(0xffffffffu, a1, 1);
  float p2 = __shfl_up_sync(0xffffffffu, a2, 1);
  float q1 = __shfl_down_sync(0xffffffffu, b1, 1);
  float q2 = __shfl_down_sync(0xffffffffu, b2, 1);
  if (lane == 0)  { p1 = NEG_INF; p2 = NEG_INF; }
  if (lane == 31) { q1 = POS_INF; q2 = POS_INF; }
  e1 = fmaxf(s_w[wid], p1);
  e2 = fmaxf(s_w[32 + wid], p2);
  e3 = fminf(s_w[64 + wid], q1);
  e4 = fminf(s_w[96 + wid], q2);
  tot1 = s_w[128]; tot2 = s_w[129]; tot3 = s_w[130]; tot4 = s_w[131];
}

__device__ __forceinline__ void bsum2(float v1, float v2, float* s_w,
                                      float& r1, float& r2) {
  int lane = threadIdx.x & 31, wid = threadIdx.x >> 5;
  __syncthreads();
#pragma unroll
  for (int o = 16; o > 0; o >>= 1) {
    v1 += __shfl_down_sync(0xffffffffu, v1, o);
    v2 += __shfl_down_sync(0xffffffffu, v2, o);
  }
  if (lane == 0) { s_w[wid] = v1; s_w[32 + wid] = v2; }
  __syncthreads();
  if (wid == 0) {
    float a = s_w[lane], b = s_w[32 + lane];
#pragma unroll
    for (int o = 16; o > 0; o >>= 1) {
      a += __shfl_down_sync(0xffffffffu, a, o);
      b += __shfl_down_sync(0xffffffffu, b, o);
    }
    if (lane == 0) { s_w[64] = a; s_w[65] = b; }
  }
  __syncthreads();
  r1 = s_w[64]; r2 = s_w[65];
}

// block reduce max & min (for rare fallback)
__device__ __forceinline__ void bred_mm(float mx, float mn, float* s_w,
                                        float& rmx, float& rmn) {
  int lane = threadIdx.x & 31, wid = threadIdx.x >> 5;
  __syncthreads();
#pragma unroll
  for (int o = 16; o > 0; o >>= 1) {
    mx = fmaxf(mx, __shfl_down_sync(0xffffffffu, mx, o));
    mn = fminf(mn, __shfl_down_sync(0xffffffffu, mn, o));
  }
  if (lane == 0) { s_w[wid] = mx; s_w[32 + wid] = mn; }
  __syncthreads();
  if (wid == 0) {
    float a = s_w[lane], b = s_w[32 + lane];
#pragma unroll
    for (int o = 16; o > 0; o >>= 1) {
      a = fmaxf(a, __shfl_down_sync(0xffffffffu, a, o));
      b = fminf(b, __shfl_down_sync(0xffffffffu, b, o));
    }
    if (lane == 0) { s_w[64] = a; s_w[65] = b; }
  }
  __syncthreads();
  rmx = s_w[64]; rmn = s_w[65];
}

// np.interp through peaks, local coords; l may be remote-negative (>= -HALF) or
// none (< -HALF); r may be remote (>= HALF, < Ln) or none (>= Ln).
__device__ __forceinline__ float seg_env(const float* h, int l, int r, int i,
                                         int& cl, int& cr, float& vl, float& vr,
                                         float remL, float remR) {
  if (r != cr) { cr = r; vr = (r >= Ln) ? 0.f : ((r >= HALF) ? remR : h[IDX(r)]); }
  if (l != cl) { cl = l; vl = (l < -HALF) ? 0.f : ((l < 0) ? remL : h[IDX(l)]); }
  if (r >= Ln) return vl;
  if (l < -HALF) return vr;
  int den = r - l;
  if (den <= 0) return vl;
  return vl + ((float)(i - l) / (float)den) * (vr - vl);
}

// ---------- main persistent kernel ----------

__global__ void __launch_bounds__(NT, 1)
emd_main(const float* __restrict__ x, float* __restrict__ out) {
  extern __shared__ float dsm[];
  float* P0 = dsm;
  float* P1 = P0 + PADL;           // ib (peak-index buffer)
  float* P2 = P1 + PADL;
  __shared__ float s_w[132];
  __shared__ float s_x[16];
  __shared__ float s_sc;

  const int blk = blockIdx.x;
  const int row = blk >> 1, half = blk & 1, pb = blk ^ 1;
  const int gbase = row * Ln + half * HALF;
  const int t = threadIdx.x, base = t * CHUNK;
  const int lane = t & 31;
  const float fdelta = half ? (float)(-HALF) : (float)HALF;  // partner-local -> my-local
  unsigned nbar = 0, nex = 0, nfb = 0;

  float* hc = P0;
  float* hn = P2;
  int* ib = (int*)P1;

  for (int i = t; i < HALF; i += NT) {
    float v = x[gbase + i];
    g_res[gbase + i] = v;
    hc[IDX(i)] = v;
  }

  // edges of the current hc array (values of h at gLo-1 and gHi)
  float ehL = (half == 1) ? x[gbase - 1] : 0.f;
  float ehR = (half == 0) ? x[gbase + HALF] : 0.f;

  // pass-1 state: per-thread running peak info + sum(h^2)
  float lu, ll, fu, fl, h2;
  auto pass1 = [&](const float* h, float eL, float eR) {
    float a = (t == 0) ? eL : h[IDX(base - 1)];
    float b = h[IDX(base)];
    int lui = -1, lli = -1;
    float fui = FNONE_R, fli = FNONE_R;
    float s = 0.f;
#pragma unroll
    for (int j = 0; j < CHUNK; j++) {
      int i = base + j;
      float c = (i + 1 < HALF) ? h[IDX(i + 1)] : eR;
      bool valid = half ? (i < HALF - 1) : (i > 0);
      bool mu = valid && (b > a) && (b > c);
      bool ml = valid && (b < a) && (b < c);
      if (mu) { lui = i; if (fui == FNONE_R) fui = (float)i; }
      if (ml) { lli = i; if (fli == FNONE_R) fli = (float)i; }
      ib[IDX(i)] = (lui + 1) | ((lli + 1) << 16);
      s += b * b;
      a = b; b = c;
    }
    lu = (lui < 0) ? FNONE_L : (float)lui;
    ll = (lli < 0) ? FNONE_L : (float)lli;
    fu = fui; fl = fli; h2 = s;
  };

  bool done = false;
  for (int k = 0; k < NIMF; k++) {
    float* outk = out + (size_t)k * BATCH * Ln + gbase;
    if (done) {
      for (int i = t; i < HALF; i += NT) outk[i] = 0.f;
      continue;
    }
    __syncthreads();
    pass1(hc, ehL, ehR);   // true edges
    bool fix = false;

    // -------- sifting --------
    for (int it = 0; it < MAXIT; it++) {
      // (A) fixup edge threads after speculative pass1
      if (fix && (t == 0 || t == NT - 1)) pass1(hc, ehL, ehR);

      // (B) local scans
      float preU, preL, sufU, sufL, lastU, lastL, firstU, firstL;
      bscan4(lu, ll, fu, fl, s_w, preU, preL, sufU, sufL, lastU, lastL, firstU, firstL);

      // (C) post exchange packet
      nex++;
      int slotx = (int)(nex & 1u);
      if (t == 0) {
        float vLU = (lastU >= 0.f) ? hc[IDX((int)lastU)] : 0.f;
        float vLL = (lastL >= 0.f) ? hc[IDX((int)lastL)] : 0.f;
        float vFU = (firstU < (float)HALF) ? hc[IDX((int)firstU)] : 0.f;
        float vFL = (firstL < (float)HALF) ? hc[IDX((int)firstL)] : 0.f;
        float* p = g_ex[slotx][blk];
        __stcg(&p[0], lastU);  __stcg(&p[1], vLU);
        __stcg(&p[2], lastL);  __stcg(&p[3], vLL);
        __stcg(&p[4], firstU); __stcg(&p[5], vFU);
        __stcg(&p[6], firstL); __stcg(&p[7], vFL);
        __threadfence();
        __stcg(&g_ep2[blk], nex);
      }
      // (D) poll partner + stage packet
      if (t < 32) {
        while (__ldcg(&g_ep2[pb]) < nex) __nanosleep(32);
        __threadfence();
        if (t < 8) s_x[t] = __ldcg(&g_ex[slotx][pb][t]);
      }
      __syncthreads();

      // (E) resolve global peak info (partner idx shifted into my coords)
      float rLU = s_x[0] + fdelta, rLL = s_x[2] + fdelta;
      float rFU = s_x[4] + fdelta, rFL = s_x[6] + fdelta;
      float remLUv = s_x[1], remLLv = s_x[3], remRUv = s_x[5], remRLv = s_x[7];
      float seedLU = half ? rLU : FNONE_L, seedLL = half ? rLL : FNONE_L;
      float seedRU = half ? FNONE_R : rFU, seedRL = half ? FNONE_R : rFL;
      int preUi = (int)fmaxf(preU, seedLU), preLi = (int)fmaxf(preL, seedLL);
      int sufUi = (int)fminf(sufU, seedRU), sufLi = (int)fminf(sufL, seedRL);
      bool manyU = fmaxf(lastU, rLU) > fminf(firstU, rFU);
      bool manyL = fmaxf(lastL, rLL) > fminf(firstL, rFL);

      float m2 = 0.f;
      if (manyU && manyL) {
        // (F) pass 2: backward walk — next-peaks + fused mean + h update into hn
        int i0 = base + CHUNK - 1;
        float b3 = hc[IDX(i0)];
        float c3 = (i0 + 1 < HALF) ? hc[IDX(i0 + 1)] : ehR;
        int ru = sufUi, rl = sufLi;
        int clU = CACHE_NONE, crU = CACHE_NONE, clL = CACHE_NONE, crL = CACHE_NONE;
        float vlU = 0.f, vrU = 0.f, vlL = 0.f, vrL = 0.f;
#pragma unroll
        for (int j = CHUNK - 1; j >= 0; j--) {
          int i = base + j;
          float a3 = (i > 0) ? hc[IDX(i - 1)] : ehL;
          bool valid = half ? (i < HALF - 1) : (i > 0);
          if (valid && (b3 > a3) && (b3 > c3)) ru = i;
          if (valid && (b3 < a3) && (b3 < c3)) rl = i;
          unsigned pk = (unsigned)ib[IDX(i)];
          int lui = (pk & 0xffffu) ? (int)(pk & 0xffffu) - 1 : preUi;
          int lli = (pk >> 16) ? (int)(pk >> 16) - 1 : preLi;
          float eu = seg_env(hc, lui, ru, i, clU, crU, vlU, vrU, remLUv, remRUv);
          float el = seg_env(hc, lli, rl, i, clL, crL, vlL, vrL, remLLv, remRLv);
          float m = 0.5f * (eu + el);
          m2 += m * m;
          hn[IDX(i)] = b3 - m;
          c3 = b3; b3 = a3;
        }
      } else {
        // rare: need partner block max/min for cummax/cummin fallback
        float bmx = NEG_INF, bmn = POS_INF;
#pragma unroll
        for (int j = 0; j < CHUNK; j++) {
          float v = hc[IDX(base + j)];
          bmx = fmaxf(bmx, v); bmn = fminf(bmn, v);
        }
        float tmx, tmn;
        bred_mm(bmx, bmn, s_w, tmx, tmn);
        nfb++;
        int slotf = (int)(nfb & 1u);
        if (t == 0) {
          __stcg(&g_fb[slotf][blk][0], tmx);
          __stcg(&g_fb[slotf][blk][1], tmn);
          __threadfence();
          __stcg(&g_epf[blk], nfb);
        }
        if (t < 32) {
          while (__ldcg(&g_epf[pb]) < nfb) __nanosleep(32);
          __threadfence();
          if (t < 2) s_x[12 + t] = __ldcg(&g_fb[slotf][pb][t]);
        }
        __syncthreads();
        float seedMax = half ? s_x[12] : NEG_INF;
        float seedMin = half ? s_x[13] : POS_INF;

        if (manyU) {
          int i0 = base + CHUNK - 1;
          float b3 = hc[IDX(i0)];
          float c3 = (i0 + 1 < HALF) ? hc[IDX(i0 + 1)] : ehR;
          int ru = sufUi, cl = CACHE_NONE, cr = CACHE_NONE;
          float vl = 0.f, vr = 0.f;
#pragma unroll
          for (int j = CHUNK - 1; j >= 0; j--) {
            int i = base + j;
            float a3 = (i > 0) ? hc[IDX(i - 1)] : ehL;
            bool valid = half ? (i < HALF - 1) : (i > 0);
            if (valid && (b3 > a3) && (b3 > c3)) ru = i;
            unsigned pk = (unsigned)ib[IDX(i)];
            int lui = (pk & 0xffffu) ? (int)(pk & 0xffffu) - 1 : preUi;
            hn[IDX(i)] = seg_env(hc, lui, ru, i, cl, cr, vl, vr, remLUv, remRUv);
            c3 = b3; b3 = a3;
          }
        } else {
          float mx = NEG_INF;
#pragma unroll
          for (int j = 0; j < CHUNK; j++) mx = fmaxf(mx, hc[IDX(base + j)]);
          float run = fmaxf(bscan_ex(mx, 1, s_w), seedMax);
#pragma unroll
          for (int j = 0; j < CHUNK; j++) {
            run = fmaxf(run, hc[IDX(base + j)]);
            hn[IDX(base + j)] = run;
          }
        }
        if (manyL) {
          int i0 = base + CHUNK - 1;
          float b3 = hc[IDX(i0)];
          float c3 = (i0 + 1 < HALF) ? hc[IDX(i0 + 1)] : ehR;
          int rl = sufLi, cl = CACHE_NONE, cr = CACHE_NONE;
          float vl = 0.f, vr = 0.f;
#pragma unroll
          for (int j = CHUNK - 1; j >= 0; j--) {
            int i = base + j;
            float a3 = (i > 0) ? hc[IDX(i - 1)] : ehL;
            bool valid = half ? (i < HALF - 1) : (i > 0);
            if (valid && (b3 < a3) && (b3 < c3)) rl = i;
            unsigned pk = (unsigned)ib[IDX(i)];
            int lli = (pk >> 16) ? (int)(pk >> 16) - 1 : preLi;
            float el = seg_env(hc, lli, rl, i, cl, cr, vl, vr, remLLv, remRLv);
            float m = 0.5f * (hn[IDX(i)] + el);
            m2 += m * m;
            hn[IDX(i)] = b3 - m;
            c3 = b3; b3 = a3;
          }
        } else {
          float mn = POS_INF;
#pragma unroll
          for (int j = 0; j < CHUNK; j++) mn = fminf(mn, hc[IDX(base + j)]);
          float run = fminf(bscan_ex(mn, 0, s_w), seedMin);
#pragma unroll
          for (int j = 0; j < CHUNK; j++) {
            int i = base + j;
            float h = hc[IDX(i)];
            run = fminf(run, h);
            float m = 0.5f * (hn[IDX(i)] + run);
            m2 += m * m;
            hn[IDX(i)] = h - m;
          }
        }
      }

      // (G) warp partials of (m2, h2)
      {
        float w1 = m2, w2 = h2;
#pragma unroll
        for (int o = 16; o > 0; o >>= 1) {
          w1 += __shfl_down_sync(0xffffffffu, w1, o);
          w2 += __shfl_down_sync(0xffffffffu, w2, o);
        }
        if (lane == 0) { s_w[t >> 5] = w1; s_w[32 + (t >> 5)] = w2; }
      }
      __syncthreads();                    // hn + partials visible
      nbar++;
      int slot = (int)(nbar & 1u);
      // (H) post partials + hn edges + epoch; global poll + decide (warp 0)
      if (t < 32) {
        float a = s_w[t], b = s_w[32 + t];
#pragma unroll
        for (int o = 16; o > 0; o >>= 1) {
          a += __shfl_down_sync(0xffffffffu, a, o);
          b += __shfl_down_sync(0xffffffffu, b, o);
        }
        if (t == 0) {
          __stcg(&g_part[slot][0][blk], a);
          __stcg(&g_part[slot][1][blk], b);
          __stcg(&g_edgeF[slot][blk], hn[IDX(0)]);
          __stcg(&g_edgeL[slot][blk], hn[IDX(HALF - 1)]);
          __threadfence();
          __stcg(&g_ep[blk], nbar);
        }
        for (;;) {
          unsigned e0 = __ldcg(&g_ep[t]);
          unsigned e1 = __ldcg(&g_ep[t + 32]);
          unsigned e2 = __ldcg(&g_ep[t + 64]);
          unsigned e3 = __ldcg(&g_ep[t + 96]);
          if (__all_sync(0xffffffffu, (e0 >= nbar) & (e1 >= nbar) & (e2 >= nbar) & (e3 >= nbar))) break;
          __nanosleep(32);
        }
        __threadfence();
        double A = (double)__ldcg(&g_part[slot][0][t]) + (double)__ldcg(&g_part[slot][0][t + 32])
                 + (double)__ldcg(&g_part[slot][0][t + 64]) + (double)__ldcg(&g_part[slot][0][t + 96]);
        double B = (double)__ldcg(&g_part[slot][1][t]) + (double)__ldcg(&g_part[slot][1][t + 32])
                 + (double)__ldcg(&g_part[slot][1][t + 64]) + (double)__ldcg(&g_part[slot][1][t + 96]);
#pragma unroll
        for (int o = 16; o > 0; o >>= 1) {
          A += __shfl_down_sync(0xffffffffu, A, o);
          B += __shfl_down_sync(0xffffffffu, B, o);
        }
        if (t == 0) s_sc = (A / (B + 1e-8) < TOLF) ? 1.f : 0.f;
        if (t == 0) s_x[14] = __ldcg(&g_edgeL[slot][pb]);   // partner last elem of hn
        if (t == 1) s_x[15] = __ldcg(&g_edgeF[slot][pb]);   // partner first elem of hn
      }
      // speculative pass 1 on hn (dummy edges; edge threads fixed next iter)
      pass1(hn, 0.f, 0.f);
      fix = true;
      __syncthreads();
      if (s_sc != 0.f) break;             // converged: keep hc
      // adopt hn as new hc; update its true edges
      if (t == 0 && half == 1) ehL = s_x[14];
      if (t == NT - 1 && half == 0) ehR = s_x[15];
      { float* tmp = hc; hc = hn; hn = tmp; }
    }

    // emit imf = hc, update residual, stage r into hn (becomes next IMF's h)
    for (int i = t; i < HALF; i += NT) {
      float h = hc[IDX(i)];
      float r = g_res[gbase + i] - h;
      outk[i] = h;
      g_res[gbase + i] = r;
      hn[IDX(i)] = r;
    }
    __syncthreads();

    // flatness: var(diff(res), ddof=1) < TOL * var(res, ddof=1), global over batch.
    // local sums exclude the cross-half boundary diff; deciders add it from edges.
    float s1 = 0.f, s2 = 0.f, d1 = 0.f, d2 = 0.f;
#pragma unroll
    for (int j = 0; j < CHUNK; j++) {
      int i = base + j;
      float v = hn[IDX(i)];
      s1 += v; s2 += v * v;
      if (i < HALF - 1) { float d = hn[IDX(i + 1)] - v; d1 += d; d2 += d * d; }
    }
    bsum2(s1, s2, s_w, s1, s2);
    bsum2(d1, d2, s_w, d1, d2);
    nbar++;
    int slot = (int)(nbar & 1u);
    if (t == 0) {
      __stcg(&g_part[slot][0][blk], s1);
      __stcg(&g_part[slot][1][blk], s2);
      __stcg(&g_part[slot][2][blk], d1);
      __stcg(&g_part[slot][3][blk], d2);
      __stcg(&g_edgeF[slot][blk], hn[IDX(0)]);          // res first elem
      __stcg(&g_edgeL[slot][blk], hn[IDX(HALF - 1)]);   // res last elem
      __threadfence();
      __stcg(&g_ep[blk], nbar);
    }
    if (t < 32) {
      for (;;) {
        unsigned e0 = __ldcg(&g_ep[t]);
        unsigned e1 = __ldcg(&g_ep[t + 32]);
        unsigned e2 = __ldcg(&g_ep[t + 64]);
        unsigned e3 = __ldcg(&g_ep[t + 96]);
        if (__all_sync(0xffffffffu, (e0 >= nbar) & (e1 >= nbar) & (e2 >= nbar) & (e3 >= nbar))) break;
        __nanosleep(32);
      }
      __threadfence();
      double S1 = 0, S2 = 0, D1 = 0, D2 = 0;
#pragma unroll
      for (int q = 0; q < 4; q++) {
        int bidx = t + 32 * q;
        S1 += (double)__ldcg(&g_part[slot][0][bidx]);
        S2 += (double)__ldcg(&g_part[slot][1][bidx]);
        D1 += (double)__ldcg(&g_part[slot][2][bidx]);
        D2 += (double)__ldcg(&g_part[slot][3][bidx]);
      }
      // boundary diffs: rows t and t+32 (deterministic, identical in every block)
#pragma unroll
      for (int q = 0; q < 2; q++) {
        int r2i = t + 32 * q;
        float e0v = __ldcg(&g_edgeL[slot][2 * r2i]);
        float e1v = __ldcg(&g_edgeF[slot][2 * r2i + 1]);
        double d = (double)e1v - (double)e0v;
        D1 += d; D2 += d * d;
      }
#pragma unroll
      for (int o = 16; o > 0; o >>= 1) {
        S1 += __shfl_down_sync(0xffffffffu, S1, o);
        S2 += __shfl_down_sync(0xffffffffu, S2, o);
        D1 += __shfl_down_sync(0xffffffffu, D1, o);
        D2 += __shfl_down_sync(0xffffffffu, D2, o);
      }
      if (t == 0) {
        double N = (double)BATCH * Ln, Nd = (double)BATCH * (Ln - 1);
        double vr = (S2 - S1 * S1 / N) / (N - 1.0);
        double vd = (D2 - D1 * D1 / Nd) / (Nd - 1.0);
        s_sc = (vd < TOLF * vr) ? 1.f : 0.f;
      }
      if (t == 0) s_x[14] = __ldcg(&g_edgeL[slot][pb]);   // partner res last
      if (t == 1) s_x[15] = __ldcg(&g_edgeF[slot][pb]);   // partner res first
    }
    __syncthreads();
    if (s_sc != 0.f) done = true;
    // next IMF's h = residual; set its true edges
    if (t == 0 && half == 1) ehL = s_x[14];
    if (t == NT - 1 && half == 0) ehR = s_x[15];
    { float* tmp = hc; hc = hn; hn = tmp; }
  }

  // residual plane
  for (int i = t; i < HALF; i += NT) out[(size_t)NIMF * BATCH * Ln + gbase + i] = g_res[gbase + i];
}

extern "C" void kernel_launch(void* const* d_in, const int* in_sizes, int n_in,
                              void* d_out, int out_size) {
  const float* x = (const float*)d_in[0];
  float* out = (float*)d_out;
  (void)in_sizes; (void)n_in; (void)out_size;
  cudaFuncSetAttribute(emd_main, cudaFuncAttributeMaxDynamicSharedMemorySize, PADL * 3 * 4);
  emd_init<<<1, NBLK>>>();
  emd_main<<<NBLK, NT, PADL * 3 * 4>>>(x, out);
}

// round 15
// speedup vs baseline: 1.6075x; 1.6075x over previous
#include <cuda_runtime.h>

#define Ln 16384
#define BATCH 64
#define NT 1024
#define CHUNK 16
#define NIMF 6
#define MAXIT 12
#define TOLF 0.05
#define NEG_INF (-3.402823466e38f)
#define POS_INF (3.402823466e38f)
#define IDX(i) ((i)+((i)>>4))
#define PADL (Ln+(Ln>>4))

__device__ unsigned g_ep[BATCH];
__device__ float g_part[2][4][BATCH];
__device__ float g_res[BATCH*Ln];

__global__ void emd_init() { if (threadIdx.x < BATCH) g_ep[threadIdx.x] = 0u; }

__device__ __forceinline__ void st_release(unsigned* p, unsigned v) {
  asm volatile("st.release.gpu.u32 [%0], %1;" :: "l"(p), "r"(v) : "memory");
}
__device__ __forceinline__ unsigned ld_acquire(const unsigned* p) {
  unsigned v;
  asm volatile("ld.acquire.gpu.u32 %0, [%1];" : "=r"(v) : "l"(p) : "memory");
  return v;
}

// ---------- block primitives ----------

// single-value exclusive prefix scan (rare fallback paths only)
__device__ __forceinline__ float bscan_ex(float v, int ismax, float* s_w) {
  const float ident = ismax ? NEG_INF : POS_INF;
  int lane = threadIdx.x & 31, wid = threadIdx.x >> 5;
  __syncthreads();
  float incl = v;
#pragma unroll
  for (int o = 1; o < 32; o <<= 1) {
    float u = __shfl_up_sync(0xffffffffu, incl, o);
    if (lane >= o) incl = ismax ? fmaxf(incl, u) : fminf(incl, u);
  }
  if (lane == 31) s_w[wid] = incl;
  __syncthreads();
  if (wid == 0) {
    float wi = s_w[lane];
#pragma unroll
    for (int o = 1; o < 32; o <<= 1) {
      float u = __shfl_up_sync(0xffffffffu, wi, o);
      if (lane >= o) wi = ismax ? fmaxf(wi, u) : fminf(wi, u);
    }
    float we = __shfl_up_sync(0xffffffffu, wi, 1);
    if (lane == 0) we = ident;
    s_w[lane] = we;
  }
  __syncthreads();
  float e = __shfl_up_sync(0xffffffffu, incl, 1);
  if (lane == 0) e = ident;
  float wp = s_w[wid];
  return ismax ? fmaxf(wp, e) : fminf(wp, e);
}

// fused quad scan: exclusive prefix-MAX on (v1,v2), exclusive suffix-MIN on (v3,v4),
// plus block-wide inclusive totals of each. 2 internal syncs.
__device__ __forceinline__ void bscan4(float v1, float v2, float v3, float v4, float* s_w,
                                       float& e1, float& e2, float& e3, float& e4,
                                       float& tot1, float& tot2, float& tot3, float& tot4) {
  int lane = threadIdx.x & 31, wid = threadIdx.x >> 5;
  float a1 = v1, a2 = v2, b1 = v3, b2 = v4;
#pragma unroll
  for (int o = 1; o < 32; o <<= 1) {
    float u1 = __shfl_up_sync(0xffffffffu, a1, o);
    float u2 = __shfl_up_sync(0xffffffffu, a2, o);
    float d1 = __shfl_down_sync(0xffffffffu, b1, o);
    float d2 = __shfl_down_sync(0xffffffffu, b2, o);
    if (lane >= o) { a1 = fmaxf(a1, u1); a2 = fmaxf(a2, u2); }
    if (lane < 32 - o) { b1 = fminf(b1, d1); b2 = fminf(b2, d2); }
  }
  if (lane == 31) { s_w[wid] = a1; s_w[32 + wid] = a2; }
  if (lane == 0)  { s_w[64 + wid] = b1; s_w[96 + wid] = b2; }
  __syncthreads();
  if (wid == 0) {
    float w1 = s_w[lane], w2 = s_w[32 + lane], w3 = s_w[64 + lane], w4 = s_w[96 + lane];
#pragma unroll
    for (int o = 1; o < 32; o <<= 1) {
      float u1 = __shfl_up_sync(0xffffffffu, w1, o);
      float u2 = __shfl_up_sync(0xffffffffu, w2, o);
      float d3 = __shfl_down_sync(0xffffffffu, w3, o);
      float d4 = __shfl_down_sync(0xffffffffu, w4, o);
      if (lane >= o) { w1 = fmaxf(w1, u1); w2 = fmaxf(w2, u2); }
      if (lane < 32 - o) { w3 = fminf(w3, d3); w4 = fminf(w4, d4); }
    }
    if (lane == 31) { s_w[128] = w1; s_w[129] = w2; }
    if (lane == 0)  { s_w[130] = w3; s_w[131] = w4; }
    float x1 = __shfl_up_sync(0xffffffffu, w1, 1);
    float x2 = __shfl_up_sync(0xffffffffu, w2, 1);
    float x3 = __shfl_down_sync(0xffffffffu, w3, 1);
    float x4 = __shfl_down_sync(0xffffffffu, w4, 1);
    if (lane == 0)  { x1 = NEG_INF; x2 = NEG_INF; }
    if (lane == 31) { x3 = POS_INF; x4 = POS_INF; }
    s_w[lane] = x1; s_w[32 + lane] = x2; s_w[64 + lane] = x3; s_w[96 + lane] = x4;
  }
  __syncthreads();
  float p1 = __shfl_up_sync(0xffffffffu, a1, 1);
  float p2 = __shfl_up_sync(0xffffffffu, a2, 1);
  float q1 = __shfl_down_sync(0xffffffffu, b1, 1);
  float q2 = __shfl_down_sync(0xffffffffu, b2, 1);
  if (lane == 0)  { p1 = NEG_INF; p2 = NEG_INF; }
  if (lane == 31) { q1 = POS_INF; q2 = POS_INF; }
  e1 = fmaxf(s_w[wid], p1);
  e2 = fmaxf(s_w[32 + wid], p2);
  e3 = fminf(s_w[64 + wid], q1);
  e4 = fminf(s_w[96 + wid], q2);
  tot1 = s_w[128]; tot2 = s_w[129]; tot3 = s_w[130]; tot4 = s_w[131];
}

__device__ __forceinline__ void bsum2(float v1, float v2, float* s_w,
                                      float& r1, float& r2) {
  int lane = threadIdx.x & 31, wid = threadIdx.x >> 5;
  __syncthreads();
#pragma unroll
  for (int o = 16; o > 0; o >>= 1) {
    v1 += __shfl_down_sync(0xffffffffu, v1, o);
    v2 += __shfl_down_sync(0xffffffffu, v2, o);
  }
  if (lane == 0) { s_w[wid] = v1; s_w[32 + wid] = v2; }
  __syncthreads();
  if (wid == 0) {
    float a = s_w[lane], b = s_w[32 + lane];
#pragma unroll
    for (int o = 16; o > 0; o >>= 1) {
      a += __shfl_down_sync(0xffffffffu, a, o);
      b += __shfl_down_sync(0xffffffffu, b, o);
    }
    if (lane == 0) { s_w[64] = a; s_w[65] = b; }
  }
  __syncthreads();
  r1 = s_w[64]; r2 = s_w[65];
}

// np.interp through peaks; vl/vr reloaded only when l/r change.
__device__ __forceinline__ float seg_env(const float* h, int l, int r, int i,
                                         int& cl, int& cr, float& vl, float& vr) {
  if (r != cr) { cr = r; vr = h[IDX(r >= Ln ? Ln - 1 : r)]; }
  if (l != cl) { cl = l; vl = h[IDX(l < 0 ? 0 : l)]; }
  if (r >= Ln) return vl;
  if (l < 0) return vr;
  int den = r - l;
  if (den <= 0) return vl;
  return vl + ((float)(i - l) / (float)den) * (vr - vl);
}

// ---------- main persistent kernel ----------

__global__ void __launch_bounds__(NT, 1)
emd_main(const float* __restrict__ x, float* __restrict__ out) {
  extern __shared__ float dsm[];
  float* P0 = dsm;
  float* P1 = P0 + PADL;           // ib (peak-index buffer)
  float* P2 = P1 + PADL;
  __shared__ float s_w[132];
  __shared__ float s_p[5][32];     // warp0's pass1 state, computed by warp1
  __shared__ float s_sc;

  const int t = threadIdx.x, row = blockIdx.x;
  const int rb = row * Ln, base = t * CHUNK;
  const int lane = t & 31;
  unsigned nbar = 0;

  float* hc = P0;
  float* hn = P2;
  int* ib = (int*)P1;

  for (int i = t; i < Ln; i += NT) {
    float v = x[rb + i];
    g_res[rb + i] = v;
    hc[IDX(i)] = v;
  }

  // pass-1 worker, explicit base + explicit outputs (so warp1 can cover warp0)
  auto pass1b = [&](const float* h, int bb,
                    float& olu, float& oll, float& ofu, float& ofl, float& oh2) {
    float a = (bb > 0) ? h[IDX(bb - 1)] : 0.f;
    float b = h[IDX(bb)];
    int lui = -1, lli = -1, fui = Ln, fli = Ln;
    float s = 0.f;
#pragma unroll
    for (int j = 0; j < CHUNK; j++) {
      int i = bb + j;
      float c = (i + 1 < Ln) ? h[IDX(i + 1)] : 0.f;
      bool valid = (i > 0) && (i < Ln - 1);
      bool mu = valid && (b > a) && (b > c);
      bool ml = valid && (b < a) && (b < c);
      if (mu) { lui = i; if (fui == Ln) fui = i; }
      if (ml) { lli = i; if (fli == Ln) fli = i; }
      ib[IDX(i)] = (lui + 1) | ((lli + 1) << 16);
      s += b * b;
      a = b; b = c;
    }
    olu = (float)lui; oll = (float)lli; ofu = (float)fui; ofl = (float)fli; oh2 = s;
  };

  float lu, ll, fu, fl, h2;

  bool done = false;
  for (int k = 0; k < NIMF; k++) {
    float* outk = out + (size_t)k * BATCH * Ln + rb;
    if (done) {
      for (int i = t; i < Ln; i += NT) outk[i] = 0.f;
      continue;
    }
    __syncthreads();          // hc fully written (init or previous emit)
    pass1b(hc, base, lu, ll, fu, fl, h2);   // all threads, incl. warp 0

    // -------- sifting --------
    for (int it = 0; it < MAXIT; it++) {
      // warp 0 picks up its pass1 state (computed by warp 1 last iteration)
      if (it > 0 && t < 32) {
        lu = s_p[0][t]; ll = s_p[1][t]; fu = s_p[2][t]; fl = s_p[3][t]; h2 = s_p[4][t];
      }

      float preU, preL, sufU, sufL, lastU, lastL, firstU, firstL;
      bscan4(lu, ll, fu, fl, s_w, preU, preL, sufU, sufL, lastU, lastL, firstU, firstL);
      int preUi = (int)fmaxf(preU, -1.f), preLi = (int)fmaxf(preL, -1.f);
      int sufUi = (int)fminf(sufU, (float)Ln), sufLi = (int)fminf(sufL, (float)Ln);
      bool manyU = lastU > firstU;    // >=2 upper peaks (block-uniform)
      bool manyL = lastL > firstL;

      float m2 = 0.f;
      if (manyU && manyL) {
        // pass 2: backward walk — next-peaks + fused mean + h update into hn
        int i0 = base + CHUNK - 1;
        float b3 = hc[IDX(i0)];
        float c3 = (i0 + 1 < Ln) ? hc[IDX(i0 + 1)] : 0.f;
        int ru = sufUi, rl = sufLi;
        int clU = -9, crU = -9, clL = -9, crL = -9;
        float vlU = 0.f, vrU = 0.f, vlL = 0.f, vrL = 0.f;
#pragma unroll
        for (int j = CHUNK - 1; j >= 0; j--) {
          int i = base + j;
          float a3 = (i > 0) ? hc[IDX(i - 1)] : 0.f;
          bool valid = (i > 0) && (i < Ln - 1);
          if (valid && (b3 > a3) && (b3 > c3)) ru = i;
          if (valid && (b3 < a3) && (b3 < c3)) rl = i;
          unsigned pk = (unsigned)ib[IDX(i)];
          int lui = (pk & 0xffffu) ? (int)(pk & 0xffffu) - 1 : preUi;
          int lli = (pk >> 16) ? (int)(pk >> 16) - 1 : preLi;
          float eu = seg_env(hc, lui, ru, i, clU, crU, vlU, vrU);
          float el = seg_env(hc, lli, rl, i, clL, crL, vlL, vrL);
          float m = 0.5f * (eu + el);
          m2 += m * m;
          hn[IDX(i)] = b3 - m;
          c3 = b3; b3 = a3;
        }
      } else {
        // rare paths: env_u -> hn, then combine with env_l
        if (manyU) {
          int i0 = base + CHUNK - 1;
          float b3 = hc[IDX(i0)];
          float c3 = (i0 + 1 < Ln) ? hc[IDX(i0 + 1)] : 0.f;
          int ru = sufUi, cl = -9, cr = -9;
          float vl = 0.f, vr = 0.f;
#pragma unroll
          for (int j = CHUNK - 1; j >= 0; j--) {
            int i = base + j;
            float a3 = (i > 0) ? hc[IDX(i - 1)] : 0.f;
            if (i > 0 && i < Ln - 1 && (b3 > a3) && (b3 > c3)) ru = i;
            unsigned pk = (unsigned)ib[IDX(i)];
            int lui = (pk & 0xffffu) ? (int)(pk & 0xffffu) - 1 : preUi;
            hn[IDX(i)] = seg_env(hc, lui, ru, i, cl, cr, vl, vr);
            c3 = b3; b3 = a3;
          }
        } else {
          float mx = NEG_INF;
#pragma unroll
          for (int j = 0; j < CHUNK; j++) mx = fmaxf(mx, hc[IDX(base + j)]);
          float run = bscan_ex(mx, 1, s_w);
#pragma unroll
          for (int j = 0; j < CHUNK; j++) {
            run = fmaxf(run, hc[IDX(base + j)]);
            hn[IDX(base + j)] = run;
          }
        }
        if (manyL) {
          int i0 = base + CHUNK - 1;
          float b3 = hc[IDX(i0)];
          float c3 = (i0 + 1 < Ln) ? hc[IDX(i0 + 1)] : 0.f;
          int rl = sufLi, cl = -9, cr = -9;
          float vl = 0.f, vr = 0.f;
#pragma unroll
          for (int j = CHUNK - 1; j >= 0; j--) {
            int i = base + j;
            float a3 = (i > 0) ? hc[IDX(i - 1)] : 0.f;
            if (i > 0 && i < Ln - 1 && (b3 < a3) && (b3 < c3)) rl = i;
            unsigned pk = (unsigned)ib[IDX(i)];
            int lli = (pk >> 16) ? (int)(pk >> 16) - 1 : preLi;
            float el = seg_env(hc, lli, rl, i, cl, cr, vl, vr);
            float m = 0.5f * (hn[IDX(i)] + el);
            m2 += m * m;
            hn[IDX(i)] = b3 - m;
            c3 = b3; b3 = a3;
          }
        } else {
          float mn = POS_INF;
#pragma unroll
          for (int j = 0; j < CHUNK; j++) mn = fminf(mn, hc[IDX(base + j)]);
          float run = bscan_ex(mn, 0, s_w);
#pragma unroll
          for (int j = 0; j < CHUNK; j++) {
            int i = base + j;
            float h = hc[IDX(i)];
            run = fminf(run, h);
            float m = 0.5f * (hn[IDX(i)] + run);
            m2 += m * m;
            hn[IDX(i)] = h - m;
          }
        }
      }

      // warp-level partials of (m2, h2) -> s_w[0..63]
      {
        float w1 = m2, w2 = h2;
#pragma unroll
        for (int o = 16; o > 0; o >>= 1) {
          w1 += __shfl_down_sync(0xffffffffu, w1, o);
          w2 += __shfl_down_sync(0xffffffffu, w2, o);
        }
        if (lane == 0) { s_w[t >> 5] = w1; s_w[32 + (t >> 5)] = w2; }
      }
      __syncthreads();                    // hn + partials visible
      nbar++;
      int slot = (int)(nbar & 1u);
      if (t < 32) {
        // finalize block sums, post (release), poll (acquire), decide
        float a = s_w[t], b = s_w[32 + t];
#pragma unroll
        for (int o = 16; o > 0; o >>= 1) {
          a += __shfl_down_sync(0xffffffffu, a, o);
          b += __shfl_down_sync(0xffffffffu, b, o);
        }
        if (t == 0) {
          __stcg(&g_part[slot][0][row], a);
          __stcg(&g_part[slot][1][row], b);
          st_release(&g_ep[row], nbar);
        }
        for (;;) {
          unsigned ea = ld_acquire(&g_ep[t]);
          unsigned eb = ld_acquire(&g_ep[t + 32]);
          if (__all_sync(0xffffffffu, (ea >= nbar) && (eb >= nbar))) break;
          __nanosleep(32);
        }
        double A = (double)__ldcg(&g_part[slot][0][t]) + (double)__ldcg(&g_part[slot][0][t + 32]);
        double B = (double)__ldcg(&g_part[slot][1][t]) + (double)__ldcg(&g_part[slot][1][t + 32]);
#pragma unroll
        for (int o = 16; o > 0; o >>= 1) {
          A += __shfl_down_sync(0xffffffffu, A, o);
          B += __shfl_down_sync(0xffffffffu, B, o);
        }
        if (t == 0) s_sc = (A / (B + 1e-8) < TOLF) ? 1.f : 0.f;
      } else {
        // speculative pass 1 on hn (overlaps warp0's poll); discarded on conv.
        pass1b(hn, base, lu, ll, fu, fl, h2);
        if (t < 64) {
          // warp 1 also covers warp 0's chunks -> smem
          float a0, a1, a2, a3, a4;
          pass1b(hn, (t - 32) * CHUNK, a0, a1, a2, a3, a4);
          s_p[0][t - 32] = a0; s_p[1][t - 32] = a1; s_p[2][t - 32] = a2;
          s_p[3][t - 32] = a3; s_p[4][t - 32] = a4;
        }
      }
      __syncthreads();
      if (s_sc != 0.f) break;             // converged: keep hc
      { float* tmp = hc; hc = hn; hn = tmp; }  // state now describes new hc
    }

    // emit imf = hc, update residual, stage r into hn (becomes next IMF's h)
    for (int i = t; i < Ln; i += NT) {
      float h = hc[IDX(i)];
      float r = g_res[rb + i] - h;
      outk[i] = h;
      g_res[rb + i] = r;
      hn[IDX(i)] = r;
    }
    __syncthreads();

    // flatness: var(diff(res), ddof=1) < TOL * var(res, ddof=1), global
    float s1 = 0.f, s2 = 0.f, d1 = 0.f, d2 = 0.f;
#pragma unroll
    for (int j = 0; j < CHUNK; j++) {
      int i = base + j;
      float v = hn[IDX(i)];
      s1 += v; s2 += v * v;
      if (i < Ln - 1) { float d = hn[IDX(i + 1)] - v; d1 += d; d2 += d * d; }
    }
    bsum2(s1, s2, s_w, s1, s2);
    bsum2(d1, d2, s_w, d1, d2);
    nbar++;
    int slot = (int)(nbar & 1u);
    if (t == 0) {
      __stcg(&g_part[slot][0][row], s1);
      __stcg(&g_part[slot][1][row], s2);
      __stcg(&g_part[slot][2][row], d1);
      __stcg(&g_part[slot][3][row], d2);
      st_release(&g_ep[row], nbar);
    }
    if (t < 32) {
      for (;;) {
        unsigned ea = ld_acquire(&g_ep[t]);
        unsigned eb = ld_acquire(&g_ep[t + 32]);
        if (__all_sync(0xffffffffu, (ea >= nbar) && (eb >= nbar))) break;
        __nanosleep(32);
      }
      double S1 = (double)__ldcg(&g_part[slot][0][t]) + (double)__ldcg(&g_part[slot][0][t + 32]);
      double S2 = (double)__ldcg(&g_part[slot][1][t]) + (double)__ldcg(&g_part[slot][1][t + 32]);
      double D1 = (double)__ldcg(&g_part[slot][2][t]) + (double)__ldcg(&g_part[slot][2][t + 32]);
      double D2 = (double)__ldcg(&g_part[slot][3][t]) + (double)__ldcg(&g_part[slot][3][t + 32]);
#pragma unroll
      for (int o = 16; o > 0; o >>= 1) {
        S1 += __shfl_down_sync(0xffffffffu, S1, o);
        S2 += __shfl_down_sync(0xffffffffu, S2, o);
        D1 += __shfl_down_sync(0xffffffffu, D1, o);
        D2 += __shfl_down_sync(0xffffffffu, D2, o);
      }
      if (t == 0) {
        double N = (double)BATCH * Ln, Nd = (double)BATCH * (Ln - 1);
        double vr = (S2 - S1 * S1 / N) / (N - 1.0);
        double vd = (D2 - D1 * D1 / Nd) / (Nd - 1.0);
        s_sc = (vd < TOLF * vr) ? 1.f : 0.f;
      }
    }
    __syncthreads();
    if (s_sc != 0.f) done = true;
    { float* tmp = hc; hc = hn; hn = tmp; }   // hc := residual (next IMF's h)
  }

  // residual plane
  for (int i = t; i < Ln; i += NT) out[(size_t)NIMF * BATCH * Ln + rb + i] = g_res[rb + i];
}

extern "C" void kernel_launch(void* const* d_in, const int* in_sizes, int n_in,
                              void* d_out, int out_size) {
  const float* x = (const float*)d_in[0];
  float* out = (float*)d_out;
  (void)in_sizes; (void)n_in; (void)out_size;
  cudaFuncSetAttribute(emd_main, cudaFuncAttributeMaxDynamicSharedMemorySize, PADL * 3 * 4);
  emd_init<<<1, BATCH>>>();
  emd_main<<<BATCH, NT, PADL * 3 * 4>>>(x, out);
}